// round 4
// baseline (speedup 1.0000x reference)
#include <cuda_runtime.h>
#include <cuda_fp16.h>

// DigitCaps routing:
//   x [128,1024,16], W [1,16,1024,16,16], B [16,1,1024] -> out [128,16,16] (fp32)
// k1:     u_hat(fp16) = einsum + fp32 c-chunk partials of sum_c u_hat  (f32x2 math)
// k_usum: reduce partials -> g_usum
// k2a:    per (b, csplit): scores -> softmax -> partial s  (pipelined tile loads)
// k2b:    reduce partials, squash, write out

#define BATCH  128
#define NCAPS  16
#define INCAPS 1024
#define DIMC   16
#define COEF   0.25f

#define K1_CB     16
#define K1_NCBLK  (INCAPS / K1_CB)   // 64
#define K2_CT     32
#define K2_SPLIT  8
#define K2_TILES  (INCAPS / (K2_CT * K2_SPLIT))  // 4

typedef unsigned long long u64;

// ---- packed fp32x2 helpers (sm_100a) --------------------------------------
__device__ __forceinline__ u64 f2fma(u64 a, u64 b, u64 c) {
    u64 d;
    asm("fma.rn.f32x2 %0, %1, %2, %3;" : "=l"(d) : "l"(a), "l"(b), "l"(c));
    return d;
}
__device__ __forceinline__ u64 f2dup(float x) {
    u64 d;
    asm("mov.b64 %0, {%1, %1};" : "=l"(d) : "f"(x));
    return d;
}
__device__ __forceinline__ u64 f2pack(float lo, float hi) {
    u64 d;
    asm("mov.b64 %0, {%1, %2};" : "=l"(d) : "f"(lo), "f"(hi));
    return d;
}
__device__ __forceinline__ float2 f2unpack(u64 v) {
    float lo, hi;
    asm("mov.b64 {%0, %1}, %2;" : "=f"(lo), "=f"(hi) : "l"(v));
    return make_float2(lo, hi);
}

// scratch
__device__ __half g_uhat[(size_t)BATCH * NCAPS * INCAPS * DIMC];    // 64 MB
__device__ float  g_part[(size_t)K1_NCBLK * BATCH * NCAPS * DIMC];  // 8 MB
__device__ float  g_usum[(size_t)BATCH * NCAPS * DIMC];             // 128 KB
__device__ float  g_spart[(size_t)K2_SPLIT * BATCH * NCAPS * DIMC]; // 1 MB

// ---------------------------------------------------------------------------
// Kernel 1: grid (64, 16) = (cblk, n), 256 threads.
// ---------------------------------------------------------------------------
__global__ __launch_bounds__(256) void k1_uhat(const float* __restrict__ x,
                                               const float* __restrict__ W) {
    __shared__ float ws[4096];   // [i][c][d]
    __shared__ float xs[4096];   // [i][c][b] (reused as red[c][b][d])

    const int t    = threadIdx.x;
    const int cblk = blockIdx.x;
    const int n    = blockIdx.y;
    const int c0   = cblk * K1_CB;

    // --- W[n, c0:c0+16, :, :] -> ws[i][c][d]
    const float4* Wg4 = (const float4*)W;
    const int wbase4 = n * 65536 + c0 * 64;
#pragma unroll
    for (int k = 0; k < 4; k++) {
        int idx4 = t + 256 * k;
        float4 v = Wg4[wbase4 + idx4];
        int flat = idx4 * 4;
        int c  = flat >> 8;
        int d  = (flat >> 4) & 15;
        int i0 = flat & 15;
        ws[((i0 + 0) * 16 + c) * 16 + d] = v.x;
        ws[((i0 + 1) * 16 + c) * 16 + d] = v.y;
        ws[((i0 + 2) * 16 + c) * 16 + d] = v.z;
        ws[((i0 + 3) * 16 + c) * 16 + d] = v.w;
    }

    const int dq = t & 3;
    const int bq = (t >> 2) & 3;
    const int cc = t >> 4;
    const float4* xg4 = (const float4*)x;

    // prefetch bt=0 x tile
    float4 xv[4];
#pragma unroll
    for (int k = 0; k < 4; k++) {
        int idx4 = t + 256 * k;
        int brow = idx4 >> 6;
        int off  = idx4 & 63;
        xv[k] = xg4[brow * 4096 + c0 * 4 + off];
    }
    __syncthreads();

    for (int bt = 0; bt < 8; bt++) {
        const int b0 = bt * 16;

        // --- scatter prefetched x -> xs[i][c][b]
#pragma unroll
        for (int k = 0; k < 4; k++) {
            int idx4 = t + 256 * k;
            int brow = idx4 >> 6;
            int off  = idx4 & 63;
            int cl = off >> 2;
            int i0 = (off & 3) * 4;
            xs[((i0 + 0) * 16 + cl) * 16 + brow] = xv[k].x;
            xs[((i0 + 1) * 16 + cl) * 16 + brow] = xv[k].y;
            xs[((i0 + 2) * 16 + cl) * 16 + brow] = xv[k].z;
            xs[((i0 + 3) * 16 + cl) * 16 + brow] = xv[k].w;
        }
        __syncthreads();

        // --- prefetch next bt
        {
            int b0n = ((bt < 7) ? bt + 1 : bt) * 16;
#pragma unroll
            for (int k = 0; k < 4; k++) {
                int idx4 = t + 256 * k;
                int brow = idx4 >> 6;
                int off  = idx4 & 63;
                xv[k] = xg4[(b0n + brow) * 4096 + c0 * 4 + off];
            }
        }

        // --- packed compute: acc[j2][d], lanes = (b even, b odd) of pair j2
        u64 ac00 = 0, ac01 = 0, ac02 = 0, ac03 = 0;   // pair 0 (b: bq*4+0, +1)
        u64 ac10 = 0, ac11 = 0, ac12 = 0, ac13 = 0;   // pair 1 (b: bq*4+2, +3)
#pragma unroll
        for (int i = 0; i < 16; i++) {
            ulonglong2 xp = *(const ulonglong2*)&xs[(i * 16 + cc) * 16 + bq * 4];
            float4 wr = *(const float4*)&ws[(i * 16 + cc) * 16 + dq * 4];
            u64 w0 = f2dup(wr.x), w1 = f2dup(wr.y), w2 = f2dup(wr.z), w3 = f2dup(wr.w);
            ac00 = f2fma(xp.x, w0, ac00); ac01 = f2fma(xp.x, w1, ac01);
            ac02 = f2fma(xp.x, w2, ac02); ac03 = f2fma(xp.x, w3, ac03);
            ac10 = f2fma(xp.y, w0, ac10); ac11 = f2fma(xp.y, w1, ac11);
            ac12 = f2fma(xp.y, w2, ac12); ac13 = f2fma(xp.y, w3, ac13);
        }

        // unpack to a[b_row][d]
        float2 p00 = f2unpack(ac00), p01 = f2unpack(ac01), p02 = f2unpack(ac02), p03 = f2unpack(ac03);
        float2 p10 = f2unpack(ac10), p11 = f2unpack(ac11), p12 = f2unpack(ac12), p13 = f2unpack(ac13);
        float a00 = p00.x, a01 = p01.x, a02 = p02.x, a03 = p03.x;   // b row 0
        float a10 = p00.y, a11 = p01.y, a12 = p02.y, a13 = p03.y;   // b row 1
        float a20 = p10.x, a21 = p11.x, a22 = p12.x, a23 = p13.x;   // b row 2
        float a30 = p10.y, a31 = p11.y, a32 = p12.y, a33 = p13.y;   // b row 3

        // --- store u_hat fp16
        {
            const int c = c0 + cc;
#define K1_ST(J, A0, A1, A2, A3)                                               \
            {                                                                  \
                size_t hidx = (((size_t)((b0 + bq * 4 + (J)) * 16 + n)) * 1024 \
                               + c) * 16 + dq * 4;                             \
                union { __half2 h[2]; uint2 u; } pk;                           \
                pk.h[0] = __floats2half2_rn(A0, A1);                           \
                pk.h[1] = __floats2half2_rn(A2, A3);                           \
                *(uint2*)(g_uhat + hidx) = pk.u;                               \
            }
            K1_ST(0, a00, a01, a02, a03)
            K1_ST(1, a10, a11, a12, a13)
            K1_ST(2, a20, a21, a22, a23)
            K1_ST(3, a30, a31, a32, a33)
#undef K1_ST
        }
        __syncthreads();   // done reading xs; reuse as red

        // --- reduce over c: red[c][b][d]
        float* red = xs;
        *(float4*)&red[(cc * 16 + bq * 4 + 0) * 16 + dq * 4] = make_float4(a00, a01, a02, a03);
        *(float4*)&red[(cc * 16 + bq * 4 + 1) * 16 + dq * 4] = make_float4(a10, a11, a12, a13);
        *(float4*)&red[(cc * 16 + bq * 4 + 2) * 16 + dq * 4] = make_float4(a20, a21, a22, a23);
        *(float4*)&red[(cc * 16 + bq * 4 + 3) * 16 + dq * 4] = make_float4(a30, a31, a32, a33);
        __syncthreads();
        {
            int bb = t >> 4, d = t & 15;
            float s = 0.f;
#pragma unroll
            for (int c2 = 0; c2 < 16; c2++) s += red[c2 * 256 + bb * 16 + d];
            g_part[cblk * 32768 + (b0 + bb) * 256 + n * 16 + d] = s;
        }
        __syncthreads();
    }
}

// ---------------------------------------------------------------------------
// k_usum: grid 128, 256 threads
// ---------------------------------------------------------------------------
__global__ __launch_bounds__(256) void k_usum() {
    const int t = threadIdx.x, b = blockIdx.x;
    const float* p = g_part + b * 256 + t;
    float a0 = 0, a1 = 0, a2 = 0, a3 = 0;
#pragma unroll
    for (int k = 0; k < 64; k += 4) {
        a0 += p[(k + 0) * 32768];
        a1 += p[(k + 1) * 32768];
        a2 += p[(k + 2) * 32768];
        a3 += p[(k + 3) * 32768];
    }
    g_usum[b * 256 + t] = (a0 + a1) + (a2 + a3);
}

// ---------------------------------------------------------------------------
// k2a: grid (128 b, 8 csplit), 256 threads, pipelined tiles
// ---------------------------------------------------------------------------
#define UH_NS 656
#define UH_CS 20

__global__ __launch_bounds__(256) void k2a_route(const float* __restrict__ Bb) {
    __shared__ float sm[11584];
    float* uhs = sm;            // 10496
    float* sco = sm + 10496;    // 544
    float* wbf = sm + 11040;    // 544

    const int t  = threadIdx.x;
    const int b  = blockIdx.x;
    const int cs = blockIdx.y;

    // score-phase mapping: usum row packed into 8 b64
    const int sn = t >> 4, scs = t & 15;
    u64 urp[8];
#pragma unroll
    for (int j = 0; j < 8; j++)
        urp[j] = f2pack(g_usum[b * 256 + sn * 16 + 2 * j],
                        g_usum[b * 256 + sn * 16 + 2 * j + 1]);

    // accumulate-phase mapping
    const int asp = t >> 6, an = (t >> 2) & 15, adq = t & 3;
    u64 sacc0 = 0, sacc1 = 0;

    const uint4* ug16 = (const uint4*)g_uhat;

    // per-thread load indices (fixed across tiles)
    int ld_nn[4], ld_cl[4], ld_d0[4];
#pragma unroll
    for (int k = 0; k < 4; k++) {
        int flat = (t + 256 * k) * 8;
        ld_nn[k] = flat >> 9;
        ld_cl[k] = (flat >> 4) & 31;
        ld_d0[k] = flat & 15;
    }

    // prefetch tile 0
    uint4 pv[4];
    {
        const int cb = cs * (K2_CT * K2_TILES);
#pragma unroll
        for (int k = 0; k < 4; k++)
            pv[k] = ug16[((((size_t)(b * 16 + ld_nn[k])) * 1024 + cb + ld_cl[k]) * 16 + ld_d0[k]) >> 3];
    }

    for (int tile = 0; tile < K2_TILES; tile++) {
        const int cb = cs * (K2_CT * K2_TILES) + tile * K2_CT;
        __syncthreads();   // prior phases done with uhs/wbf

        // --- store prefetched fp16 tile -> uhs fp32
#pragma unroll
        for (int k = 0; k < 4; k++) {
            const __half2* hp = (const __half2*)&pv[k];
            float2 f0 = __half22float2(hp[0]);
            float2 f1 = __half22float2(hp[1]);
            float2 f2 = __half22float2(hp[2]);
            float2 f3 = __half22float2(hp[3]);
            float* dst = &uhs[ld_nn[k] * UH_NS + ld_cl[k] * UH_CS + ld_d0[k]];
            *(float4*)(dst + 0) = make_float4(f0.x, f0.y, f1.x, f1.y);
            *(float4*)(dst + 4) = make_float4(f2.x, f2.y, f3.x, f3.y);
        }
        __syncthreads();

        // --- prefetch next tile (overlaps scores/softmax/accumulate)
        if (tile + 1 < K2_TILES) {
            const int cbn = cb + K2_CT;
#pragma unroll
            for (int k = 0; k < 4; k++)
                pv[k] = ug16[((((size_t)(b * 16 + ld_nn[k])) * 1024 + cbn + ld_cl[k]) * 16 + ld_d0[k]) >> 3];
        }

        // --- scores[c][n] = COEF * <usum[n], uhat[n][c]>  (packed dot)
#pragma unroll
        for (int p = 0; p < 2; p++) {
            int c = scs + p * 16;
            const float* u = &uhs[sn * UH_NS + c * UH_CS];
            ulonglong2 u01 = *(const ulonglong2*)(u + 0);
            ulonglong2 u23 = *(const ulonglong2*)(u + 8);
            u64 dacc = f2fma(u01.x, urp[0], 0ULL);
            dacc = f2fma(u01.y, urp[1], dacc);
            u64 dac2 = f2fma(u23.x, urp[2], 0ULL);
            dac2 = f2fma(u23.y, urp[3], dac2);
            const float* u2 = u;  // second half uses urp[4..7] with offsets 16..31? no: d=16 only
            (void)u2;
            // remaining 8 d values
            ulonglong2 u45 = *(const ulonglong2*)(u + 4);   // d 4..7 overlap? no-no
            (void)u45;
            float2 s1 = f2unpack(dacc);
            float2 s2 = f2unpack(dac2);
            // NOTE: d runs 0..15 -> pairs 0..7; u01 covers d0..3, u23 covers d8..11.
            // Load the middle and tail pairs explicitly:
            ulonglong2 umid = *(const ulonglong2*)(u + 4);   // d4..7
            ulonglong2 utl  = *(const ulonglong2*)(u + 12);  // d12..15
            u64 dm = f2fma(umid.x, urp[2], 0ULL);
            dm = f2fma(umid.y, urp[3], dm);
            u64 dt = f2fma(utl.x, urp[6], 0ULL);
            dt = f2fma(utl.y, urp[7], dt);
            // fix pair indices for u23 (d8..11 -> urp[4],urp[5])
            u64 dh = f2fma(u23.x, urp[4], 0ULL);
            dh = f2fma(u23.y, urp[5], dh);
            float2 sm1 = f2unpack(dm);
            float2 sh  = f2unpack(dh);
            float2 st  = f2unpack(dt);
            float dot = (s1.x + s1.y) + (sm1.x + sm1.y) + (sh.x + sh.y) + (st.x + st.y);
            (void)s2;
            sco[c * 17 + sn] = COEF * dot;
        }
        __syncthreads();

        // --- softmax over n (per c) + add B -> wbf[c][n]
        if (t < 32) {
            int c = t;
            float v[16];
            float m = -1e30f;
#pragma unroll
            for (int nn = 0; nn < 16; nn++) { v[nn] = sco[c * 17 + nn]; m = fmaxf(m, v[nn]); }
            float s = 0.f;
#pragma unroll
            for (int nn = 0; nn < 16; nn++) { v[nn] = expf(v[nn] - m); s += v[nn]; }
            float inv = 1.0f / s;
#pragma unroll
            for (int nn = 0; nn < 16; nn++)
                wbf[c * 17 + nn] = v[nn] * inv + Bb[nn * 1024 + cb + c];
        }
        __syncthreads();

        // --- s[n][d] += (c+B) * uhat  (packed)
#pragma unroll
        for (int j = 0; j < 8; j++) {
            int cc2 = asp * 8 + j;
            u64 w = f2dup(wbf[cc2 * 17 + an]);
            ulonglong2 uv = *(const ulonglong2*)&uhs[an * UH_NS + cc2 * UH_CS + adq * 4];
            sacc0 = f2fma(uv.x, w, sacc0);
            sacc1 = f2fma(uv.y, w, sacc1);
        }
    }
    __syncthreads();

    // --- reduce 4 asp partials -> g_spart
    float2 q0 = f2unpack(sacc0), q1 = f2unpack(sacc1);
    float* spart = uhs;
    *(float4*)&spart[asp * 256 + an * 16 + adq * 4] = make_float4(q0.x, q0.y, q1.x, q1.y);
    __syncthreads();
    g_spart[cs * 32768 + b * 256 + t] =
        spart[t] + spart[256 + t] + spart[512 + t] + spart[768 + t];
}

// ---------------------------------------------------------------------------
// k2b: reduce csplits, squash, write out
// ---------------------------------------------------------------------------
__global__ __launch_bounds__(256) void k2b_finish(float* __restrict__ out) {
    __shared__ float sfin[256];
    __shared__ float scale[16];
    const int t = threadIdx.x, b = blockIdx.x;

    const float* p = g_spart + b * 256 + t;
    float a0 = 0, a1 = 0;
#pragma unroll
    for (int k = 0; k < 8; k += 2) {
        a0 += p[(k + 0) * 32768];
        a1 += p[(k + 1) * 32768];
    }
    sfin[t] = a0 + a1;
    __syncthreads();

    if (t < 16) {
        float sq = 0.f;
#pragma unroll
        for (int d = 0; d < 16; d++) { float z = sfin[t * 16 + d]; sq += z * z; }
        float norm = sqrtf(sq);
        scale[t] = (1.0f - expf(-norm)) * rsqrtf(sq + 1e-8f);
    }
    __syncthreads();

    out[b * 256 + t] = scale[t >> 4] * sfin[t];
}

// ---------------------------------------------------------------------------
extern "C" void kernel_launch(void* const* d_in, const int* in_sizes, int n_in,
                              void* d_out, int out_size) {
    const float* x = (const float*)d_in[0];
    const float* W = (const float*)d_in[1];
    const float* B = (const float*)d_in[2];
    float* out = (float*)d_out;

    k1_uhat<<<dim3(K1_NCBLK, NCAPS), 256>>>(x, W);
    k_usum<<<BATCH, 256>>>();
    k2a_route<<<dim3(BATCH, K2_SPLIT), 256>>>(B);
    k2b_finish<<<BATCH, 256>>>(out);
}

// round 6
// speedup vs baseline: 1.2400x; 1.2400x over previous
#include <cuda_runtime.h>
#include <cuda_fp16.h>

// DigitCaps routing:
//   x [128,1024,16], W [1,16,1024,16,16], B [16,1,1024] -> out [128,16,16] (fp32)

#define BATCH  128
#define NCAPS  16
#define INCAPS 1024
#define DIMC   16
#define COEF   0.25f

#define K1_CB     16
#define K1_NCBLK  64
#define K2_CT     32
#define K2_SPLIT  16
#define K2_TILES  2    // 1024 / (32*16)

typedef unsigned long long u64;
typedef unsigned int u32;

__device__ __forceinline__ u64 f2fma(u64 a, u64 b, u64 c) {
    u64 d;
    asm("fma.rn.f32x2 %0, %1, %2, %3;" : "=l"(d) : "l"(a), "l"(b), "l"(c));
    return d;
}

__device__ __forceinline__ u32 h2_bits(__half2 h) {
    union { __half2 h; u32 u; } cv;
    cv.h = h;
    return cv.u;
}

// scratch
__device__ __half g_uhat[(size_t)BATCH * NCAPS * INCAPS * DIMC];    // [b][n][c][d] fp16, 64 MB
__device__ float  g_part[(size_t)K1_NCBLK * BATCH * NCAPS * DIMC];  // [cblk][b][n*16+d], 8 MB
__device__ float  g_usum[(size_t)BATCH * NCAPS * DIMC];             // 128 KB
__device__ float  g_spart[(size_t)K2_SPLIT * BATCH * NCAPS * DIMC]; // 2 MB

// ---------------------------------------------------------------------------
// Kernel 1: grid (64 cblk, 16 n), 512 threads = 16 warps.
// warp = c (one c per warp), lane = b (32 b per bt iter, 4 iters).
// ws[c][d*16+i] in gmem order; all W reads are warp-broadcast LDS.128.
// x read straight to registers. u_hat stored as one 32B chunk per lane.
// ---------------------------------------------------------------------------
__global__ __launch_bounds__(512, 2) void k1_uhat(const float* __restrict__ x,
                                                  const float* __restrict__ W) {
    __shared__ float ws[4096];          // [c][d*16+i], 16 KB
    __shared__ u32   red[16 * 32 * 9];  // half2 [w][l][dp], pad 9 -> 18 KB

    const int t = threadIdx.x;
    const int w = t >> 5;        // c-local = warp id
    const int l = t & 31;        // b within bt chunk
    const int cblk = blockIdx.x;
    const int n    = blockIdx.y;
    const int c0   = cblk * K1_CB;
    const int c    = c0 + w;

    // --- load W tile (linear, conflict-free)
    const float4* Wg4 = (const float4*)W;
    float4* ws4 = (float4*)ws;
    const int wb4 = n * 65536 + c0 * 64;
    ws4[t]       = Wg4[wb4 + t];
    ws4[t + 512] = Wg4[wb4 + t + 512];

    // --- prefetch bt=0 x row: x[b=l, c, 0:16]
    const float4* xg4 = (const float4*)x;
    float4 xa = xg4[l * 4096 + c * 4 + 0];
    float4 xb = xg4[l * 4096 + c * 4 + 1];
    float4 xc = xg4[l * 4096 + c * 4 + 2];
    float4 xd = xg4[l * 4096 + c * 4 + 3];
    __syncthreads();

    const float* wsc = ws + w * 256;
    uint4* ug = (uint4*)g_uhat;

#pragma unroll
    for (int bt = 0; bt < 4; bt++) {
        const int b = bt * 32 + l;

        union { float4 f[4]; u64 q[8]; } X;
        X.f[0] = xa; X.f[1] = xb; X.f[2] = xc; X.f[3] = xd;

        // prefetch next bt (overlaps compute)
        if (bt < 3) {
            int bn = (bt + 1) * 32 + l;
            xa = xg4[bn * 4096 + c * 4 + 0];
            xb = xg4[bn * 4096 + c * 4 + 1];
            xc = xg4[bn * 4096 + c * 4 + 2];
            xd = xg4[bn * 4096 + c * 4 + 3];
        }

        u32 out[8];
#pragma unroll
        for (int dp = 0; dp < 8; dp++) {
            float v[2];
#pragma unroll
            for (int h = 0; h < 2; h++) {
                const int d = dp * 2 + h;
                union { float4 f[4]; u64 q[8]; } Wv;
                Wv.f[0] = *(const float4*)&wsc[d * 16 + 0];
                Wv.f[1] = *(const float4*)&wsc[d * 16 + 4];
                Wv.f[2] = *(const float4*)&wsc[d * 16 + 8];
                Wv.f[3] = *(const float4*)&wsc[d * 16 + 12];
                u64 sA = f2fma(X.q[0], Wv.q[0], 0ULL);
                u64 sB = f2fma(X.q[1], Wv.q[1], 0ULL);
                sA = f2fma(X.q[2], Wv.q[2], sA);
                sB = f2fma(X.q[3], Wv.q[3], sB);
                sA = f2fma(X.q[4], Wv.q[4], sA);
                sB = f2fma(X.q[5], Wv.q[5], sB);
                sA = f2fma(X.q[6], Wv.q[6], sA);
                sB = f2fma(X.q[7], Wv.q[7], sB);
                float2 fa = *(float2*)&sA;
                float2 fb = *(float2*)&sB;
                v[h] = (fa.x + fa.y) + (fb.x + fb.y);
            }
            out[dp] = h2_bits(__floats2half2_rn(v[0], v[1]));
        }

        // --- store u_hat: 32B contiguous per lane (one sector)
        {
            size_t u4 = ((size_t)(b * 16 + n) * 1024 + c) * 2;
            ug[u4]     = make_uint4(out[0], out[1], out[2], out[3]);
            ug[u4 + 1] = make_uint4(out[4], out[5], out[6], out[7]);
        }

        // --- c-partials: red[w][l][dp] (half2), 9-stride conflict-free
#pragma unroll
        for (int p = 0; p < 8; p++) red[w * 288 + l * 9 + p] = out[p];
        __syncthreads();

        if (t < 256) {
            const int b2 = t >> 3, dp2 = t & 7;
            float s0 = 0.f, s1 = 0.f;
#pragma unroll
            for (int w2 = 0; w2 < 16; w2++) {
                __half2 h = *(__half2*)&red[w2 * 288 + b2 * 9 + dp2];
                float2 f = __half22float2(h);
                s0 += f.x; s1 += f.y;
            }
            int gi = cblk * 32768 + (bt * 32 + b2) * 256 + n * 16 + dp2 * 2;
            *(float2*)&g_part[gi] = make_float2(s0, s1);
        }
        __syncthreads();
    }
}

// ---------------------------------------------------------------------------
// k_usum: grid 128 (b), 256 threads: usum[b][nd] = sum of 64 cblk partials
// ---------------------------------------------------------------------------
__global__ __launch_bounds__(256) void k_usum() {
    const int t = threadIdx.x, b = blockIdx.x;
    const float* p = g_part + b * 256 + t;
    float a0 = 0, a1 = 0, a2 = 0, a3 = 0;
#pragma unroll
    for (int k = 0; k < 64; k += 4) {
        a0 += p[(k + 0) * 32768];
        a1 += p[(k + 1) * 32768];
        a2 += p[(k + 2) * 32768];
        a3 += p[(k + 3) * 32768];
    }
    g_usum[b * 256 + t] = (a0 + a1) + (a2 + a3);
}

// ---------------------------------------------------------------------------
// k2a: grid (128 b, 16 csplit), 256 threads, 2 tiles of 32 c.
// uhs kept fp16 in smem (uint4 slots, c-stride 3, n-stride 97) -> 24.8 KB.
// ---------------------------------------------------------------------------
__global__ __launch_bounds__(256) void k2a_route(const float* __restrict__ Bb) {
    __shared__ uint4 uhs[16 * 97];      // fp16 tile [n][c][2 slots]
    __shared__ float sco[544];          // [c][17]
    __shared__ float wbf[544];

    const int t  = threadIdx.x;
    const int b  = blockIdx.x;
    const int cs = blockIdx.y;

    // score-phase mapping + usum row in regs
    const int sn = t >> 4, scs = t & 15;
    float ur[16];
#pragma unroll
    for (int j = 0; j < 16; j++) ur[j] = g_usum[b * 256 + sn * 16 + j];

    // accumulate-phase mapping
    const int asp = t >> 6, an = (t >> 2) & 15, adq = t & 3;
    float sacc0 = 0, sacc1 = 0, sacc2 = 0, sacc3 = 0;

    const uint4* ug = (const uint4*)g_uhat;

    int ld_nn[4], ld_cl[4], ld_dh[4];
#pragma unroll
    for (int k = 0; k < 4; k++) {
        int flat = (t + 256 * k) * 8;
        ld_nn[k] = flat >> 9;
        ld_cl[k] = (flat >> 4) & 31;
        ld_dh[k] = (flat >> 3) & 1;
    }

    // prefetch tile 0
    uint4 pv[4];
    {
        const int cb = cs * 64;
#pragma unroll
        for (int k = 0; k < 4; k++)
            pv[k] = ug[((size_t)(b * 16 + ld_nn[k]) * 1024 + cb + ld_cl[k]) * 2 + ld_dh[k]];
    }

#pragma unroll
    for (int tile = 0; tile < K2_TILES; tile++) {
        const int cb = cs * 64 + tile * K2_CT;
        __syncthreads();

        // --- store prefetched tile
#pragma unroll
        for (int k = 0; k < 4; k++)
            uhs[ld_nn[k] * 97 + ld_cl[k] * 3 + ld_dh[k]] = pv[k];
        __syncthreads();

        // --- prefetch next tile
        if (tile + 1 < K2_TILES) {
            const int cbn = cb + K2_CT;
#pragma unroll
            for (int k = 0; k < 4; k++)
                pv[k] = ug[((size_t)(b * 16 + ld_nn[k]) * 1024 + cbn + ld_cl[k]) * 2 + ld_dh[k]];
        }

        // --- scores[c][n] = COEF * <usum[n], uhat[n][c]>
#pragma unroll
        for (int p = 0; p < 2; p++) {
            int cx = scs + p * 16;
            uint4 ua = uhs[sn * 97 + cx * 3 + 0];
            uint4 ub = uhs[sn * 97 + cx * 3 + 1];
            const __half2* ha = (const __half2*)&ua;
            const __half2* hb = (const __half2*)&ub;
            float dot = 0.f;
#pragma unroll
            for (int j = 0; j < 4; j++) {
                float2 fa = __half22float2(ha[j]);
                float2 fb = __half22float2(hb[j]);
                dot += fa.x * ur[2 * j] + fa.y * ur[2 * j + 1];
                dot += fb.x * ur[8 + 2 * j] + fb.y * ur[9 + 2 * j];
            }
            sco[cx * 17 + sn] = COEF * dot;
        }
        __syncthreads();

        // --- softmax over n (per c) + add B
        if (t < 32) {
            int cx = t;
            float v[16];
            float m = -1e30f;
#pragma unroll
            for (int nn = 0; nn < 16; nn++) { v[nn] = sco[cx * 17 + nn]; m = fmaxf(m, v[nn]); }
            float s = 0.f;
#pragma unroll
            for (int nn = 0; nn < 16; nn++) { v[nn] = expf(v[nn] - m); s += v[nn]; }
            float inv = 1.0f / s;
#pragma unroll
            for (int nn = 0; nn < 16; nn++)
                wbf[cx * 17 + nn] = v[nn] * inv + Bb[nn * 1024 + cb + cx];
        }
        __syncthreads();

        // --- s[n][d] += (c+B) * uhat
        const __half2* uh2 = (const __half2*)uhs;
#pragma unroll
        for (int j = 0; j < 8; j++) {
            int cc2 = asp * 8 + j;
            float wv = wbf[cc2 * 17 + an];
            int h2i = (an * 97 + cc2 * 3) * 4 + adq * 2;
            float2 f0 = __half22float2(uh2[h2i]);
            float2 f1 = __half22float2(uh2[h2i + 1]);
            sacc0 += wv * f0.x; sacc1 += wv * f0.y;
            sacc2 += wv * f1.x; sacc3 += wv * f1.y;
        }
    }
    __syncthreads();

    // --- reduce 4 asp partials -> g_spart (reuse uhs region)
    float* spart = (float*)uhs;
    *(float4*)&spart[asp * 256 + an * 16 + adq * 4] = make_float4(sacc0, sacc1, sacc2, sacc3);
    __syncthreads();
    g_spart[cs * 32768 + b * 256 + t] =
        spart[t] + spart[256 + t] + spart[512 + t] + spart[768 + t];
}

// ---------------------------------------------------------------------------
// k2b: reduce 16 csplits, squash, write out
// ---------------------------------------------------------------------------
__global__ __launch_bounds__(256) void k2b_finish(float* __restrict__ out) {
    __shared__ float sfin[256];
    __shared__ float scale[16];
    const int t = threadIdx.x, b = blockIdx.x;

    const float* p = g_spart + b * 256 + t;
    float a0 = 0, a1 = 0, a2 = 0, a3 = 0;
#pragma unroll
    for (int k = 0; k < K2_SPLIT; k += 4) {
        a0 += p[(k + 0) * 32768];
        a1 += p[(k + 1) * 32768];
        a2 += p[(k + 2) * 32768];
        a3 += p[(k + 3) * 32768];
    }
    sfin[t] = (a0 + a1) + (a2 + a3);
    __syncthreads();

    if (t < 16) {
        float sq = 0.f;
#pragma unroll
        for (int d = 0; d < 16; d++) { float z = sfin[t * 16 + d]; sq += z * z; }
        float norm = sqrtf(sq);
        scale[t] = (1.0f - expf(-norm)) * rsqrtf(sq + 1e-8f);
    }
    __syncthreads();

    out[b * 256 + t] = scale[t >> 4] * sfin[t];
}

// ---------------------------------------------------------------------------
extern "C" void kernel_launch(void* const* d_in, const int* in_sizes, int n_in,
                              void* d_out, int out_size) {
    const float* x = (const float*)d_in[0];
    const float* W = (const float*)d_in[1];
    const float* B = (const float*)d_in[2];
    float* out = (float*)d_out;

    k1_uhat<<<dim3(K1_NCBLK, NCAPS), 512>>>(x, W);
    k_usum<<<BATCH, 256>>>();
    k2a_route<<<dim3(BATCH, K2_SPLIT), 256>>>(B);
    k2b_finish<<<BATCH, 256>>>(out);
}

// round 7
// speedup vs baseline: 1.3241x; 1.0678x over previous
#include <cuda_runtime.h>
#include <cuda_fp16.h>

// DigitCaps routing:
//   x [128,1024,16], W [1,16,1024,16,16], B [16,1,1024] -> out [128,16,16] (fp32)

#define BATCH  128
#define NCAPS  16
#define INCAPS 1024
#define DIMC   16
#define COEF   0.25f

#define K1_CB     8
#define K1_NCBLK  128
#define K2_CT     32
#define K2_SPLIT  16
#define K2_TILES  2    // 1024 / (32*16)

typedef unsigned long long u64;
typedef unsigned int u32;

__device__ __forceinline__ u64 f2fma(u64 a, u64 b, u64 c) {
    u64 d;
    asm("fma.rn.f32x2 %0, %1, %2, %3;" : "=l"(d) : "l"(a), "l"(b), "l"(c));
    return d;
}

__device__ __forceinline__ u32 h2_bits(__half2 h) {
    union { __half2 h; u32 u; } cv;
    cv.h = h;
    return cv.u;
}

// scratch
__device__ __half g_uhat[(size_t)BATCH * NCAPS * INCAPS * DIMC];    // [b][n][c][d] fp16, 64 MB
__device__ float  g_part[(size_t)K1_NCBLK * BATCH * NCAPS * DIMC];  // [cblk][b][n*16+d], 16 MB
__device__ float  g_usum[(size_t)BATCH * NCAPS * DIMC];             // 128 KB
__device__ float  g_spart[(size_t)K2_SPLIT * BATCH * NCAPS * DIMC]; // 2 MB

// ---------------------------------------------------------------------------
// Kernel 1: grid (128 cblk, 16 n), 256 threads = 8 warps.
// warp = c (one c per warp), lane = b. W reads are warp-broadcast LDS.128,
// shared across a pair of b-tiles. x gmem->registers, double-buffered.
// 128-reg cap (launch_bounds 256,2): no spills by construction.
// ---------------------------------------------------------------------------
__global__ __launch_bounds__(256, 2) void k1_uhat(const float* __restrict__ x,
                                                  const float* __restrict__ W) {
    __shared__ float ws[2048];          // [8c][16d][16i], 8 KB
    __shared__ u32   red[2 * 8 * 288];  // [bt2][w][l*9+dp] half2, 18.4 KB

    const int t = threadIdx.x;
    const int w = t >> 5;        // c-local = warp id (0..7)
    const int l = t & 31;        // b lane
    const int cblk = blockIdx.x;
    const int n    = blockIdx.y;
    const int c0   = cblk * K1_CB;
    const int c    = c0 + w;

    // --- load W tile (512 float4, linear, conflict-free)
    const float4* Wg4 = (const float4*)W;
    float4* ws4 = (float4*)ws;
    const int wb4 = n * 65536 + c0 * 64;
    ws4[t]       = Wg4[wb4 + t];
    ws4[t + 256] = Wg4[wb4 + t + 256];

    const float4* xg4 = (const float4*)x;
    uint4* ug = (uint4*)g_uhat;
    const float* wsc = ws + w * 256;

    // --- load pair-0 x rows (bt 0 and 1)
    float4 X0[4], X1[4];
#pragma unroll
    for (int k = 0; k < 4; k++) {
        X0[k] = xg4[(l) * 4096 + c * 4 + k];
        X1[k] = xg4[(32 + l) * 4096 + c * 4 + k];
    }
    __syncthreads();   // ws ready

#pragma unroll
    for (int p = 0; p < 2; p++) {
        union { float4 f[4]; u64 q[8]; } A, B;
#pragma unroll
        for (int k = 0; k < 4; k++) { A.f[k] = X0[k]; B.f[k] = X1[k]; }

        // prefetch pair-1 (overlaps compute)
        if (p == 0) {
#pragma unroll
            for (int k = 0; k < 4; k++) {
                X0[k] = xg4[(64 + l) * 4096 + c * 4 + k];
                X1[k] = xg4[(96 + l) * 4096 + c * 4 + k];
            }
        }

        u32 out0[8], out1[8];
#pragma unroll
        for (int dp = 0; dp < 8; dp++) {
            float v00, v01, v10, v11;
#pragma unroll
            for (int h = 0; h < 2; h++) {
                const int d = dp * 2 + h;
                union { float4 f[4]; u64 q[8]; } Wv;
                Wv.f[0] = *(const float4*)&wsc[d * 16 + 0];
                Wv.f[1] = *(const float4*)&wsc[d * 16 + 4];
                Wv.f[2] = *(const float4*)&wsc[d * 16 + 8];
                Wv.f[3] = *(const float4*)&wsc[d * 16 + 12];
                // bt even
                u64 sA = f2fma(A.q[0], Wv.q[0], 0ULL);
                u64 sB = f2fma(A.q[1], Wv.q[1], 0ULL);
                sA = f2fma(A.q[2], Wv.q[2], sA);
                sB = f2fma(A.q[3], Wv.q[3], sB);
                sA = f2fma(A.q[4], Wv.q[4], sA);
                sB = f2fma(A.q[5], Wv.q[5], sB);
                sA = f2fma(A.q[6], Wv.q[6], sA);
                sB = f2fma(A.q[7], Wv.q[7], sB);
                // bt odd
                u64 tA = f2fma(B.q[0], Wv.q[0], 0ULL);
                u64 tB = f2fma(B.q[1], Wv.q[1], 0ULL);
                tA = f2fma(B.q[2], Wv.q[2], tA);
                tB = f2fma(B.q[3], Wv.q[3], tB);
                tA = f2fma(B.q[4], Wv.q[4], tA);
                tB = f2fma(B.q[5], Wv.q[5], tB);
                tA = f2fma(B.q[6], Wv.q[6], tA);
                tB = f2fma(B.q[7], Wv.q[7], tB);
                float2 fa = *(float2*)&sA, fb = *(float2*)&sB;
                float2 ga = *(float2*)&tA, gb = *(float2*)&tB;
                float ve = (fa.x + fa.y) + (fb.x + fb.y);
                float vo = (ga.x + ga.y) + (gb.x + gb.y);
                if (h == 0) { v00 = ve; v10 = vo; } else { v01 = ve; v11 = vo; }
            }
            out0[dp] = h2_bits(__floats2half2_rn(v00, v01));
            out1[dp] = h2_bits(__floats2half2_rn(v10, v11));
        }

        // --- store u_hat (two 32B chunks per lane)
        {
            const int b0 = p * 64 + l;
            const int b1 = p * 64 + 32 + l;
            size_t u40 = ((size_t)(b0 * 16 + n) * 1024 + c) * 2;
            size_t u41 = ((size_t)(b1 * 16 + n) * 1024 + c) * 2;
            ug[u40]     = make_uint4(out0[0], out0[1], out0[2], out0[3]);
            ug[u40 + 1] = make_uint4(out0[4], out0[5], out0[6], out0[7]);
            ug[u41]     = make_uint4(out1[0], out1[1], out1[2], out1[3]);
            ug[u41 + 1] = make_uint4(out1[4], out1[5], out1[6], out1[7]);
        }

        // --- c-partials via red (stride-9, conflict-free)
#pragma unroll
        for (int q = 0; q < 8; q++) {
            red[(0 * 8 + w) * 288 + l * 9 + q] = out0[q];
            red[(1 * 8 + w) * 288 + l * 9 + q] = out1[q];
        }
        __syncthreads();
        {
            const int b2 = t >> 3, dp2 = t & 7;
#pragma unroll
            for (int bt2 = 0; bt2 < 2; bt2++) {
                float s0 = 0.f, s1 = 0.f;
#pragma unroll
                for (int w2 = 0; w2 < 8; w2++) {
                    __half2 hv = *(__half2*)&red[(bt2 * 8 + w2) * 288 + b2 * 9 + dp2];
                    float2 f = __half22float2(hv);
                    s0 += f.x; s1 += f.y;
                }
                int gb = p * 64 + bt2 * 32 + b2;
                *(float2*)&g_part[cblk * 32768 + gb * 256 + n * 16 + dp2 * 2] =
                    make_float2(s0, s1);
            }
        }
        __syncthreads();
    }
}

// ---------------------------------------------------------------------------
// k_usum: grid 128 (b), 256 threads: usum[b][nd] = sum of 128 cblk partials
// ---------------------------------------------------------------------------
__global__ __launch_bounds__(256) void k_usum() {
    const int t = threadIdx.x, b = blockIdx.x;
    const float* p = g_part + b * 256 + t;
    float a0 = 0, a1 = 0, a2 = 0, a3 = 0;
#pragma unroll
    for (int k = 0; k < K1_NCBLK; k += 4) {
        a0 += p[(size_t)(k + 0) * 32768];
        a1 += p[(size_t)(k + 1) * 32768];
        a2 += p[(size_t)(k + 2) * 32768];
        a3 += p[(size_t)(k + 3) * 32768];
    }
    g_usum[b * 256 + t] = (a0 + a1) + (a2 + a3);
}

// ---------------------------------------------------------------------------
// k2a: grid (128 b, 16 csplit), 256 threads, 2 tiles of 32 c.
// uhs kept fp16 in smem (uint4 slots, c-stride 3, n-stride 97) -> 24.8 KB.
// ---------------------------------------------------------------------------
__global__ __launch_bounds__(256) void k2a_route(const float* __restrict__ Bb) {
    __shared__ uint4 uhs[16 * 97];
    __shared__ float sco[544];
    __shared__ float wbf[544];

    const int t  = threadIdx.x;
    const int b  = blockIdx.x;
    const int cs = blockIdx.y;

    const int sn = t >> 4, scs = t & 15;
    float ur[16];
#pragma unroll
    for (int j = 0; j < 16; j++) ur[j] = g_usum[b * 256 + sn * 16 + j];

    const int asp = t >> 6, an = (t >> 2) & 15, adq = t & 3;
    float sacc0 = 0, sacc1 = 0, sacc2 = 0, sacc3 = 0;

    const uint4* ug = (const uint4*)g_uhat;

    int ld_nn[4], ld_cl[4], ld_dh[4];
#pragma unroll
    for (int k = 0; k < 4; k++) {
        int flat = (t + 256 * k) * 8;
        ld_nn[k] = flat >> 9;
        ld_cl[k] = (flat >> 4) & 31;
        ld_dh[k] = (flat >> 3) & 1;
    }

    uint4 pv[4];
    {
        const int cb = cs * 64;
#pragma unroll
        for (int k = 0; k < 4; k++)
            pv[k] = ug[((size_t)(b * 16 + ld_nn[k]) * 1024 + cb + ld_cl[k]) * 2 + ld_dh[k]];
    }

#pragma unroll
    for (int tile = 0; tile < K2_TILES; tile++) {
        const int cb = cs * 64 + tile * K2_CT;
        __syncthreads();

#pragma unroll
        for (int k = 0; k < 4; k++)
            uhs[ld_nn[k] * 97 + ld_cl[k] * 3 + ld_dh[k]] = pv[k];
        __syncthreads();

        if (tile + 1 < K2_TILES) {
            const int cbn = cb + K2_CT;
#pragma unroll
            for (int k = 0; k < 4; k++)
                pv[k] = ug[((size_t)(b * 16 + ld_nn[k]) * 1024 + cbn + ld_cl[k]) * 2 + ld_dh[k]];
        }

        // --- scores
#pragma unroll
        for (int p = 0; p < 2; p++) {
            int cx = scs + p * 16;
            uint4 ua = uhs[sn * 97 + cx * 3 + 0];
            uint4 ub = uhs[sn * 97 + cx * 3 + 1];
            const __half2* ha = (const __half2*)&ua;
            const __half2* hb = (const __half2*)&ub;
            float dot = 0.f;
#pragma unroll
            for (int j = 0; j < 4; j++) {
                float2 fa = __half22float2(ha[j]);
                float2 fb = __half22float2(hb[j]);
                dot += fa.x * ur[2 * j] + fa.y * ur[2 * j + 1];
                dot += fb.x * ur[8 + 2 * j] + fb.y * ur[9 + 2 * j];
            }
            sco[cx * 17 + sn] = COEF * dot;
        }
        __syncthreads();

        // --- softmax over n + add B
        if (t < 32) {
            int cx = t;
            float v[16];
            float m = -1e30f;
#pragma unroll
            for (int nn = 0; nn < 16; nn++) { v[nn] = sco[cx * 17 + nn]; m = fmaxf(m, v[nn]); }
            float s = 0.f;
#pragma unroll
            for (int nn = 0; nn < 16; nn++) { v[nn] = expf(v[nn] - m); s += v[nn]; }
            float inv = 1.0f / s;
#pragma unroll
            for (int nn = 0; nn < 16; nn++)
                wbf[cx * 17 + nn] = v[nn] * inv + Bb[nn * 1024 + cb + cx];
        }
        __syncthreads();

        // --- weighted accumulate
        const __half2* uh2 = (const __half2*)uhs;
#pragma unroll
        for (int j = 0; j < 8; j++) {
            int cc2 = asp * 8 + j;
            float wv = wbf[cc2 * 17 + an];
            int h2i = (an * 97 + cc2 * 3) * 4 + adq * 2;
            float2 f0 = __half22float2(uh2[h2i]);
            float2 f1 = __half22float2(uh2[h2i + 1]);
            sacc0 += wv * f0.x; sacc1 += wv * f0.y;
            sacc2 += wv * f1.x; sacc3 += wv * f1.y;
        }
    }
    __syncthreads();

    float* spart = (float*)uhs;
    *(float4*)&spart[asp * 256 + an * 16 + adq * 4] = make_float4(sacc0, sacc1, sacc2, sacc3);
    __syncthreads();
    g_spart[cs * 32768 + b * 256 + t] =
        spart[t] + spart[256 + t] + spart[512 + t] + spart[768 + t];
}

// ---------------------------------------------------------------------------
// k2b: reduce 16 csplits, squash, write out
// ---------------------------------------------------------------------------
__global__ __launch_bounds__(256) void k2b_finish(float* __restrict__ out) {
    __shared__ float sfin[256];
    __shared__ float scale[16];
    const int t = threadIdx.x, b = blockIdx.x;

    const float* p = g_spart + b * 256 + t;
    float a0 = 0, a1 = 0, a2 = 0, a3 = 0;
#pragma unroll
    for (int k = 0; k < K2_SPLIT; k += 4) {
        a0 += p[(k + 0) * 32768];
        a1 += p[(k + 1) * 32768];
        a2 += p[(k + 2) * 32768];
        a3 += p[(k + 3) * 32768];
    }
    sfin[t] = (a0 + a1) + (a2 + a3);
    __syncthreads();

    if (t < 16) {
        float sq = 0.f;
#pragma unroll
        for (int d = 0; d < 16; d++) { float z = sfin[t * 16 + d]; sq += z * z; }
        float norm = sqrtf(sq);
        scale[t] = (1.0f - expf(-norm)) * rsqrtf(sq + 1e-8f);
    }
    __syncthreads();

    out[b * 256 + t] = scale[t >> 4] * sfin[t];
}

// ---------------------------------------------------------------------------
extern "C" void kernel_launch(void* const* d_in, const int* in_sizes, int n_in,
                              void* d_out, int out_size) {
    const float* x = (const float*)d_in[0];
    const float* W = (const float*)d_in[1];
    const float* B = (const float*)d_in[2];
    float* out = (float*)d_out;

    k1_uhat<<<dim3(K1_NCBLK, NCAPS), 256>>>(x, W);
    k_usum<<<BATCH, 256>>>();
    k2a_route<<<dim3(BATCH, K2_SPLIT), 256>>>(B);
    k2b_finish<<<BATCH, 256>>>(out);
}